// round 1
// baseline (speedup 1.0000x reference)
#include <cuda_runtime.h>
#include <cuda_bf16.h>
#include <math.h>

// Problem constants: pred/target are (32, 3, 512, 512) fp32.
#define B      32
#define H      512
#define W      512
#define PLANE  (H * W)           // 262144
#define IMG    (3 * PLANE)       // one image's element count
#define NPIX   (B * PLANE)       // 8388608 output pixels

#define TILE   32                // 32x32 output tile per block
#define HALO_W (TILE + 2)        // 34
#define TPB    256               // block = (32, 8)
#define TILES_X (W / TILE)       // 16
#define TILES_Y (H / TILE)       // 16
#define NBLOCKS (B * TILES_X * TILES_Y)  // 8192

__device__ float g_partials[NBLOCKS];

__global__ __launch_bounds__(TPB) void edge_loss_kernel(
    const float* __restrict__ pred, const float* __restrict__ tgt)
{
    __shared__ float gp[HALO_W][HALO_W];
    __shared__ float gt[HALO_W][HALO_W];

    const int b   = blockIdx.z;
    const int ty0 = blockIdx.y * TILE;
    const int tx0 = blockIdx.x * TILE;
    const int tid = threadIdx.y * 32 + threadIdx.x;

    const float* pr = pred + (size_t)b * IMG;
    const float* tr = tgt  + (size_t)b * IMG;

    // Fill grayscale tiles (34x34, zero padding outside image).
    #pragma unroll
    for (int i = tid; i < HALO_W * HALO_W; i += TPB) {
        const int ly = i / HALO_W;
        const int lx = i - ly * HALO_W;
        const int gy = ty0 - 1 + ly;
        const int gx = tx0 - 1 + lx;
        float vp = 0.0f, vt = 0.0f;
        if ((unsigned)gy < (unsigned)H && (unsigned)gx < (unsigned)W) {
            const int o = gy * W + gx;
            vp = 0.299f * pr[o] + 0.587f * pr[o + PLANE] + 0.114f * pr[o + 2 * PLANE];
            vt = 0.299f * tr[o] + 0.587f * tr[o + PLANE] + 0.114f * tr[o + 2 * PLANE];
        }
        gp[ly][lx] = vp;
        gt[ly][lx] = vt;
    }
    __syncthreads();

    // Each thread: 4 output pixels (rows ty, ty+8, ty+16, ty+24).
    float acc = 0.0f;
    const int c = threadIdx.x + 1;
    #pragma unroll
    for (int k = 0; k < 4; k++) {
        const int r = threadIdx.y + k * 8 + 1;

        float a00 = gp[r - 1][c - 1], a01 = gp[r - 1][c], a02 = gp[r - 1][c + 1];
        float a10 = gp[r    ][c - 1],                     a12 = gp[r    ][c + 1];
        float a20 = gp[r + 1][c - 1], a21 = gp[r + 1][c], a22 = gp[r + 1][c + 1];
        float ex = (a02 - a00) + 2.0f * (a12 - a10) + (a22 - a20);
        float ey = (a20 - a00) + 2.0f * (a21 - a01) + (a22 - a02);
        float mp = sqrtf(ex * ex + ey * ey);

        float b00 = gt[r - 1][c - 1], b01 = gt[r - 1][c], b02 = gt[r - 1][c + 1];
        float b10 = gt[r    ][c - 1],                     b12 = gt[r    ][c + 1];
        float b20 = gt[r + 1][c - 1], b21 = gt[r + 1][c], b22 = gt[r + 1][c + 1];
        float fx = (b02 - b00) + 2.0f * (b12 - b10) + (b22 - b20);
        float fy = (b20 - b00) + 2.0f * (b21 - b01) + (b22 - b02);
        float mt = sqrtf(fx * fx + fy * fy);

        acc += fabsf(mp - mt);
    }

    // Block reduction: warp shuffle then cross-warp.
    #pragma unroll
    for (int off = 16; off > 0; off >>= 1)
        acc += __shfl_down_sync(0xffffffffu, acc, off);

    __shared__ float wsum[8];
    const int lane = tid & 31;
    const int wid  = tid >> 5;
    if (lane == 0) wsum[wid] = acc;
    __syncthreads();
    if (tid < 8) {
        float v = wsum[tid];
        #pragma unroll
        for (int off = 4; off > 0; off >>= 1)
            v += __shfl_down_sync(0x000000ffu, v, off);
        if (tid == 0) {
            const int bid = (blockIdx.z * TILES_Y + blockIdx.y) * TILES_X + blockIdx.x;
            g_partials[bid] = v;
        }
    }
}

// Deterministic final reduction: fixed-order strided fp64 sums.
__global__ __launch_bounds__(256) void edge_loss_reduce(float* __restrict__ out)
{
    __shared__ double s[256];
    double a = 0.0;
    for (int i = threadIdx.x; i < NBLOCKS; i += 256)
        a += (double)g_partials[i];
    s[threadIdx.x] = a;
    __syncthreads();
    #pragma unroll
    for (int st = 128; st > 0; st >>= 1) {
        if (threadIdx.x < st) s[threadIdx.x] += s[threadIdx.x + st];
        __syncthreads();
    }
    if (threadIdx.x == 0)
        out[0] = (float)(s[0] / (double)NPIX);
}

extern "C" void kernel_launch(void* const* d_in, const int* in_sizes, int n_in,
                              void* d_out, int out_size)
{
    const float* pred = (const float*)d_in[0];
    const float* tgt  = (const float*)d_in[1];
    float* out = (float*)d_out;

    dim3 grid(TILES_X, TILES_Y, B);
    dim3 block(32, 8);
    edge_loss_kernel<<<grid, block>>>(pred, tgt);
    edge_loss_reduce<<<1, 256>>>(out);
}

// round 2
// speedup vs baseline: 1.1090x; 1.1090x over previous
#include <cuda_runtime.h>
#include <cuda_bf16.h>
#include <math.h>

// pred/target: (32, 3, 512, 512) fp32. Output: scalar fp32 mean |sobel(gray(p)) - sobel(gray(t))|.
#define B      32
#define H      512
#define W      512
#define PLANE  (H * W)
#define IMG    (3 * PLANE)
#define NPIX   (B * PLANE)        // 8388608

#define RT     16                 // output rows per block
#define TILES  (H / RT)           // 32
#define NBLK   (B * TILES)        // 1024
#define TPB    256
#define NROWS  (RT + 2)           // 18 staged rows (with y halo)
#define SROW   520                // smem row stride in floats (data at [4..515], halos at 3 and 516)
#define SMEM_BYTES (2 * NROWS * SROW * 4)   // 74880

__device__ float        g_partials[NBLK];
__device__ unsigned int g_count = 0;

__device__ __forceinline__ float fsqrt_approx(float x) {
    float r;
    asm("sqrt.approx.f32 %0, %1;" : "=f"(r) : "f"(x));
    return r;
}

// Load a 6-float window [c0-1 .. c0+4] from a staged gray row (16B-aligned center float4).
#define LOADW(sbase, rowidx, wdst) do {                                  \
    const float* _rp = (sbase) + (rowidx) * SROW + coff;                 \
    float4 _v = *(const float4*)_rp;                                     \
    (wdst)[0] = _rp[-1];                                                 \
    (wdst)[1] = _v.x; (wdst)[2] = _v.y; (wdst)[3] = _v.z; (wdst)[4] = _v.w; \
    (wdst)[5] = _rp[4];                                                  \
} while (0)

__global__ __launch_bounds__(TPB) void edge_loss_fused(
    const float* __restrict__ pred, const float* __restrict__ tgt,
    float* __restrict__ out)
{
    extern __shared__ float sm[];
    float* gp = sm;                    // [NROWS][SROW] gray(pred)
    float* gt = sm + NROWS * SROW;     // [NROWS][SROW] gray(target)

    const int tile = blockIdx.x;       // row-tile within image
    const int b    = blockIdx.y;       // batch
    const int gy0  = tile * RT;
    const int tid  = threadIdx.x;

    const float* pr = pred + (size_t)b * IMG;
    const float* tr = tgt  + (size_t)b * IMG;

    // ---- Stage 18 full-width gray rows (float4 loads, fully coalesced) ----
    #pragma unroll 3
    for (int idx = tid; idx < NROWS * 128; idx += TPB) {
        const int row = idx >> 7;       // 0..17
        const int q   = idx & 127;      // float4 index within row
        const int gy  = gy0 - 1 + row;
        float4 vp = make_float4(0.f, 0.f, 0.f, 0.f);
        float4 vt = make_float4(0.f, 0.f, 0.f, 0.f);
        if ((unsigned)gy < (unsigned)H) {
            const size_t ro = (size_t)gy * W;
            float4 r0 = ((const float4*)(pr + ro))[q];
            float4 g0 = ((const float4*)(pr + PLANE + ro))[q];
            float4 b0 = ((const float4*)(pr + 2 * PLANE + ro))[q];
            vp.x = 0.299f * r0.x + 0.587f * g0.x + 0.114f * b0.x;
            vp.y = 0.299f * r0.y + 0.587f * g0.y + 0.114f * b0.y;
            vp.z = 0.299f * r0.z + 0.587f * g0.z + 0.114f * b0.z;
            vp.w = 0.299f * r0.w + 0.587f * g0.w + 0.114f * b0.w;
            float4 r1 = ((const float4*)(tr + ro))[q];
            float4 g1 = ((const float4*)(tr + PLANE + ro))[q];
            float4 b1 = ((const float4*)(tr + 2 * PLANE + ro))[q];
            vt.x = 0.299f * r1.x + 0.587f * g1.x + 0.114f * b1.x;
            vt.y = 0.299f * r1.y + 0.587f * g1.y + 0.114f * b1.y;
            vt.z = 0.299f * r1.z + 0.587f * g1.z + 0.114f * b1.z;
            vt.w = 0.299f * r1.w + 0.587f * g1.w + 0.114f * b1.w;
        }
        *(float4*)(gp + row * SROW + 4 + 4 * q) = vp;
        *(float4*)(gt + row * SROW + 4 + 4 * q) = vt;
        if (q == 0) {   // x halos (zero padding)
            gp[row * SROW + 3]   = 0.f;  gp[row * SROW + 516] = 0.f;
            gt[row * SROW + 3]   = 0.f;  gt[row * SROW + 516] = 0.f;
        }
    }
    __syncthreads();

    // ---- Compute: each thread owns a 4-wide column quad and 8 rows, rolling in y ----
    const int ct   = tid & 127;        // column-quad id: cols [4*ct, 4*ct+4)
    const int rh   = tid >> 7;         // row half: 0 or 1
    const int coff = 4 + 4 * ct;       // smem offset of quad center (16B aligned)
    const int rb   = rh * 8;           // output local rows rb..rb+7 -> smem rows rb..rb+9

    float wp[3][6], wt[3][6];
    LOADW(gp, rb + 0, wp[0]);  LOADW(gt, rb + 0, wt[0]);
    LOADW(gp, rb + 1, wp[1]);  LOADW(gt, rb + 1, wt[1]);

    float acc = 0.0f;
    #pragma unroll
    for (int k = 0; k < 8; k++) {
        const int it = k % 3, im = (k + 1) % 3, ib = (k + 2) % 3;
        LOADW(gp, rb + k + 2, wp[ib]);
        LOADW(gt, rb + k + 2, wt[ib]);
        #pragma unroll
        for (int j = 0; j < 4; j++) {
            float ex = (wp[it][j + 2] - wp[it][j])
                     + 2.0f * (wp[im][j + 2] - wp[im][j])
                     + (wp[ib][j + 2] - wp[ib][j]);
            float ey = (wp[ib][j] - wp[it][j])
                     + 2.0f * (wp[ib][j + 1] - wp[it][j + 1])
                     + (wp[ib][j + 2] - wp[it][j + 2]);
            float mp = fsqrt_approx(ex * ex + ey * ey);

            float fx = (wt[it][j + 2] - wt[it][j])
                     + 2.0f * (wt[im][j + 2] - wt[im][j])
                     + (wt[ib][j + 2] - wt[ib][j]);
            float fy = (wt[ib][j] - wt[it][j])
                     + 2.0f * (wt[ib][j + 1] - wt[it][j + 1])
                     + (wt[ib][j + 2] - wt[it][j + 2]);
            float mt = fsqrt_approx(fx * fx + fy * fy);

            acc += fabsf(mp - mt);
        }
    }

    // ---- Block reduction (fixed order) ----
    #pragma unroll
    for (int off = 16; off > 0; off >>= 1)
        acc += __shfl_down_sync(0xffffffffu, acc, off);

    __shared__ float wsum[8];
    const int lane = tid & 31, wid = tid >> 5;
    if (lane == 0) wsum[wid] = acc;
    __syncthreads();
    if (tid < 8) {
        float v = wsum[tid];
        #pragma unroll
        for (int off = 4; off > 0; off >>= 1)
            v += __shfl_down_sync(0x000000ffu, v, off);
        if (tid == 0)
            g_partials[b * TILES + tile] = v;
    }

    // ---- Fused grid-wide final reduction: last block sums all partials (fp64, fixed order) ----
    __shared__ bool isLast;
    if (tid == 0) {
        __threadfence();
        unsigned int old = atomicAdd(&g_count, 1u);
        isLast = (old == (unsigned)(NBLK - 1));
    }
    __syncthreads();
    if (isLast) {
        __shared__ double ds[TPB];
        double a = 0.0;
        #pragma unroll
        for (int i = 0; i < NBLK / TPB; i++)
            a += (double)__ldcg(&g_partials[tid + i * TPB]);
        ds[tid] = a;
        __syncthreads();
        #pragma unroll
        for (int st = TPB / 2; st > 0; st >>= 1) {
            if (tid < st) ds[tid] += ds[tid + st];
            __syncthreads();
        }
        if (tid == 0) {
            out[0] = (float)(ds[0] / (double)NPIX);
            g_count = 0;   // self-reset for graph replay
        }
    }
}

extern "C" void kernel_launch(void* const* d_in, const int* in_sizes, int n_in,
                              void* d_out, int out_size)
{
    const float* pred = (const float*)d_in[0];
    const float* tgt  = (const float*)d_in[1];
    float* out = (float*)d_out;

    cudaFuncSetAttribute(edge_loss_fused,
                         cudaFuncAttributeMaxDynamicSharedMemorySize, SMEM_BYTES);

    dim3 grid(TILES, B);
    edge_loss_fused<<<grid, TPB, SMEM_BYTES>>>(pred, tgt, out);
}